// round 1
// baseline (speedup 1.0000x reference)
#include <cuda_runtime.h>
#include <math.h>

// Problem dims (fixed by the reference)
#define M_ROWS 8192      // B*L = 4*2048
#define D_IN   1536
#define D_H    4096
#define D_OUT  2048
#define KCB    8192      // codebook size
#define NCB    (KCB/128) // 64 column blocks in the score GEMM

// -------- scratch (device globals; no allocations allowed) ----------
__device__ float g_h[(size_t)M_ROWS * D_H];      // 134 MB
__device__ float g_z[(size_t)M_ROWS * D_OUT];    // 67 MB
__device__ float g_znorm[M_ROWS];
__device__ float g_cnorm[KCB];
__device__ float g_pval[(size_t)M_ROWS * NCB];
__device__ int   g_pidx[(size_t)M_ROWS * NCB];
__device__ int   g_bidx[M_ROWS];

// -------- tiling ----------
#define BK   16
#define SPAD 4
#define LDA  (128 + SPAD)   // 132 floats; keeps 16B alignment per k-row (132*4=528, 528%16==0)

// =====================================================================
// Generic C[m][n] = sum_k A[m,k]*B[n,k] + bias[n]  (both operands K-major)
// 128x128 tile, BK=16, 256 threads, 8x8 per thread, smem double-buffered.
// =====================================================================
__global__ __launch_bounds__(256) void sgemm_bias(
    const float* __restrict__ A, const float* __restrict__ B,
    const float* __restrict__ bias, float* __restrict__ C,
    int M, int N, int K)
{
    __shared__ float As[2][BK][LDA];
    __shared__ float Bs[2][BK][LDA];

    const int tid = threadIdx.x;
    const int tx  = tid & 15;
    const int ty  = tid >> 4;
    const int bm  = blockIdx.y * 128;
    const int bn  = blockIdx.x * 128;

    float acc[8][8];
#pragma unroll
    for (int i = 0; i < 8; ++i)
#pragma unroll
        for (int j = 0; j < 8; ++j) acc[i][j] = 0.f;

    const int r0 = tid >> 2;        // 0..63
    const int c4 = (tid & 3) * 4;   // 0,4,8,12

    float4 ra[2], rb[2];
    // prologue: tile 0
#pragma unroll
    for (int i = 0; i < 2; ++i) {
        int r = r0 + i * 64;
        ra[i] = *(const float4*)(A + (size_t)(bm + r) * K + c4);
        rb[i] = *(const float4*)(B + (size_t)(bn + r) * K + c4);
    }
#pragma unroll
    for (int i = 0; i < 2; ++i) {
        int r = r0 + i * 64;
#pragma unroll
        for (int j = 0; j < 4; ++j) {
            As[0][c4 + j][r] = ((const float*)&ra[i])[j];
            Bs[0][c4 + j][r] = ((const float*)&rb[i])[j];
        }
    }
    __syncthreads();

    const int nt = K / BK;
    for (int t = 0; t < nt; ++t) {
        const int cur = t & 1, nxt = cur ^ 1;
        if (t + 1 < nt) {
            const int k0 = (t + 1) * BK;
#pragma unroll
            for (int i = 0; i < 2; ++i) {
                int r = r0 + i * 64;
                ra[i] = *(const float4*)(A + (size_t)(bm + r) * K + k0 + c4);
                rb[i] = *(const float4*)(B + (size_t)(bn + r) * K + k0 + c4);
            }
        }
#pragma unroll
        for (int k = 0; k < BK; ++k) {
            float a[8], b[8];
            *(float4*)&a[0] = *(const float4*)&As[cur][k][ty * 8];
            *(float4*)&a[4] = *(const float4*)&As[cur][k][ty * 8 + 4];
            *(float4*)&b[0] = *(const float4*)&Bs[cur][k][tx * 8];
            *(float4*)&b[4] = *(const float4*)&Bs[cur][k][tx * 8 + 4];
#pragma unroll
            for (int i = 0; i < 8; ++i)
#pragma unroll
                for (int j = 0; j < 8; ++j)
                    acc[i][j] = fmaf(a[i], b[j], acc[i][j]);
        }
        if (t + 1 < nt) {
#pragma unroll
            for (int i = 0; i < 2; ++i) {
                int r = r0 + i * 64;
#pragma unroll
                for (int j = 0; j < 4; ++j) {
                    As[nxt][c4 + j][r] = ((const float*)&ra[i])[j];
                    Bs[nxt][c4 + j][r] = ((const float*)&rb[i])[j];
                }
            }
        }
        __syncthreads();
    }

    // epilogue: + bias, vectorized stores
    const float4 bj0 = *(const float4*)(bias + bn + tx * 8);
    const float4 bj1 = *(const float4*)(bias + bn + tx * 8 + 4);
#pragma unroll
    for (int i = 0; i < 8; ++i) {
        const int gm = bm + ty * 8 + i;
        float4 v0, v1;
        v0.x = acc[i][0] + bj0.x; v0.y = acc[i][1] + bj0.y;
        v0.z = acc[i][2] + bj0.z; v0.w = acc[i][3] + bj0.w;
        v1.x = acc[i][4] + bj1.x; v1.y = acc[i][5] + bj1.y;
        v1.z = acc[i][6] + bj1.z; v1.w = acc[i][7] + bj1.w;
        *(float4*)(C + (size_t)gm * N + bn + tx * 8)     = v0;
        *(float4*)(C + (size_t)gm * N + bn + tx * 8 + 4) = v1;
    }
}

// =====================================================================
// Reductions / normalization
// =====================================================================
__device__ __forceinline__ float block_reduce_sum(float v)
{
    __shared__ float sh[8];
    const int lane = threadIdx.x & 31, w = threadIdx.x >> 5;
#pragma unroll
    for (int o = 16; o; o >>= 1) v += __shfl_xor_sync(0xffffffffu, v, o);
    if (lane == 0) sh[w] = v;
    __syncthreads();
    if (w == 0) {
        float x = (lane < 8) ? sh[lane] : 0.f;
#pragma unroll
        for (int o = 4; o; o >>= 1) x += __shfl_xor_sync(0xffffffffu, x, o);
        if (lane == 0) sh[0] = x;
    }
    __syncthreads();
    float r = sh[0];
    __syncthreads();   // protect sh before next call
    return r;
}

__device__ __forceinline__ float gelu_exact(float y)
{
    return 0.5f * y * (1.0f + erff(y * 0.70710678118654752440f));
}

// per-row LN (two-pass, matching reference) then exact GELU, in place. D=4096.
__global__ __launch_bounds__(256) void ln_gelu4096(
    float* __restrict__ H, const float* __restrict__ gm, const float* __restrict__ bt)
{
    float* x = H + (size_t)blockIdx.x * D_H;
    const int tid = threadIdx.x;
    float v[16];
#pragma unroll
    for (int i = 0; i < 4; ++i)
        *(float4*)&v[i * 4] = *(const float4*)(x + tid * 4 + i * 1024);
    float s = 0.f;
#pragma unroll
    for (int i = 0; i < 16; ++i) s += v[i];
    s = block_reduce_sum(s);
    const float mu = s * (1.0f / 4096.0f);
    float q = 0.f;
#pragma unroll
    for (int i = 0; i < 16; ++i) { float d = v[i] - mu; q += d * d; }
    q = block_reduce_sum(q);
    const float inv = 1.0f / sqrtf(q * (1.0f / 4096.0f) + 1e-5f);
#pragma unroll
    for (int i = 0; i < 4; ++i) {
        const float4 gg = *(const float4*)(gm + tid * 4 + i * 1024);
        const float4 bb = *(const float4*)(bt + tid * 4 + i * 1024);
        float4 o;
        o.x = gelu_exact((v[i*4+0] - mu) * inv * gg.x + bb.x);
        o.y = gelu_exact((v[i*4+1] - mu) * inv * gg.y + bb.y);
        o.z = gelu_exact((v[i*4+2] - mu) * inv * gg.z + bb.z);
        o.w = gelu_exact((v[i*4+3] - mu) * inv * gg.w + bb.w);
        *(float4*)(x + tid * 4 + i * 1024) = o;
    }
}

// per-row LN for z (D=2048), in place; also writes znorm = sum(zf*zf)
__global__ __launch_bounds__(256) void ln_znorm2048(
    float* __restrict__ Z, const float* __restrict__ gm, const float* __restrict__ bt)
{
    float* x = Z + (size_t)blockIdx.x * D_OUT;
    const int tid = threadIdx.x;
    float v[8];
#pragma unroll
    for (int i = 0; i < 2; ++i)
        *(float4*)&v[i * 4] = *(const float4*)(x + tid * 4 + i * 1024);
    float s = 0.f;
#pragma unroll
    for (int i = 0; i < 8; ++i) s += v[i];
    s = block_reduce_sum(s);
    const float mu = s * (1.0f / 2048.0f);
    float q = 0.f;
#pragma unroll
    for (int i = 0; i < 8; ++i) { float d = v[i] - mu; q += d * d; }
    q = block_reduce_sum(q);
    const float inv = 1.0f / sqrtf(q * (1.0f / 2048.0f) + 1e-5f);
    float nrm = 0.f;
#pragma unroll
    for (int i = 0; i < 2; ++i) {
        const float4 gg = *(const float4*)(gm + tid * 4 + i * 1024);
        const float4 bb = *(const float4*)(bt + tid * 4 + i * 1024);
        float4 o;
        o.x = (v[i*4+0] - mu) * inv * gg.x + bb.x;
        o.y = (v[i*4+1] - mu) * inv * gg.y + bb.y;
        o.z = (v[i*4+2] - mu) * inv * gg.z + bb.z;
        o.w = (v[i*4+3] - mu) * inv * gg.w + bb.w;
        nrm += o.x*o.x + o.y*o.y + o.z*o.z + o.w*o.w;
        *(float4*)(x + tid * 4 + i * 1024) = o;
    }
    nrm = block_reduce_sum(nrm);
    if (tid == 0) g_znorm[blockIdx.x] = nrm;
}

// ||codebook_k||^2 for all k
__global__ __launch_bounds__(256) void cnorm2048(const float* __restrict__ CB)
{
    const float* c = CB + (size_t)blockIdx.x * D_OUT;
    float s = 0.f;
#pragma unroll
    for (int i = 0; i < 2; ++i) {
        const float4 u = *(const float4*)(c + threadIdx.x * 4 + i * 1024);
        s += u.x*u.x + u.y*u.y + u.z*u.z + u.w*u.w;
    }
    s = block_reduce_sum(s);
    if (threadIdx.x == 0) g_cnorm[blockIdx.x] = s;
}

// =====================================================================
// Score GEMM with fused per-(rowtile,coltile) argmin partials.
// dist = (znorm + cnorm) - 2*dot, first-min tie-break (ascending k).
// =====================================================================
__global__ __launch_bounds__(256) void score_argmin(
    const float* __restrict__ A,   // z  [8192, 2048]
    const float* __restrict__ B)   // cb [8192, 2048]
{
    __shared__ float As[2][BK][LDA];
    __shared__ float Bs[2][BK][LDA];

    const int tid = threadIdx.x;
    const int tx  = tid & 15;
    const int ty  = tid >> 4;
    const int bm  = blockIdx.y * 128;
    const int bn  = blockIdx.x * 128;
    const int K   = D_OUT;

    float acc[8][8];
#pragma unroll
    for (int i = 0; i < 8; ++i)
#pragma unroll
        for (int j = 0; j < 8; ++j) acc[i][j] = 0.f;

    const int r0 = tid >> 2;
    const int c4 = (tid & 3) * 4;

    float4 ra[2], rb[2];
#pragma unroll
    for (int i = 0; i < 2; ++i) {
        int r = r0 + i * 64;
        ra[i] = *(const float4*)(A + (size_t)(bm + r) * K + c4);
        rb[i] = *(const float4*)(B + (size_t)(bn + r) * K + c4);
    }
#pragma unroll
    for (int i = 0; i < 2; ++i) {
        int r = r0 + i * 64;
#pragma unroll
        for (int j = 0; j < 4; ++j) {
            As[0][c4 + j][r] = ((const float*)&ra[i])[j];
            Bs[0][c4 + j][r] = ((const float*)&rb[i])[j];
        }
    }
    __syncthreads();

    const int nt = K / BK;
    for (int t = 0; t < nt; ++t) {
        const int cur = t & 1, nxt = cur ^ 1;
        if (t + 1 < nt) {
            const int k0 = (t + 1) * BK;
#pragma unroll
            for (int i = 0; i < 2; ++i) {
                int r = r0 + i * 64;
                ra[i] = *(const float4*)(A + (size_t)(bm + r) * K + k0 + c4);
                rb[i] = *(const float4*)(B + (size_t)(bn + r) * K + k0 + c4);
            }
        }
#pragma unroll
        for (int k = 0; k < BK; ++k) {
            float a[8], b[8];
            *(float4*)&a[0] = *(const float4*)&As[cur][k][ty * 8];
            *(float4*)&a[4] = *(const float4*)&As[cur][k][ty * 8 + 4];
            *(float4*)&b[0] = *(const float4*)&Bs[cur][k][tx * 8];
            *(float4*)&b[4] = *(const float4*)&Bs[cur][k][tx * 8 + 4];
#pragma unroll
            for (int i = 0; i < 8; ++i)
#pragma unroll
                for (int j = 0; j < 8; ++j)
                    acc[i][j] = fmaf(a[i], b[j], acc[i][j]);
        }
        if (t + 1 < nt) {
#pragma unroll
            for (int i = 0; i < 2; ++i) {
                int r = r0 + i * 64;
#pragma unroll
                for (int j = 0; j < 4; ++j) {
                    As[nxt][c4 + j][r] = ((const float*)&ra[i])[j];
                    Bs[nxt][c4 + j][r] = ((const float*)&rb[i])[j];
                }
            }
        }
        __syncthreads();
    }

    // epilogue: distances + per-row argmin across the 128-wide column tile
    __syncthreads();
    float* sval = (float*)As;   // 128*16 floats fits in As
    int*   sidx = (int*)Bs;

    float cn[8];
#pragma unroll
    for (int j = 0; j < 8; ++j) cn[j] = g_cnorm[bn + tx * 8 + j];

#pragma unroll
    for (int i = 0; i < 8; ++i) {
        const int lr = ty * 8 + i;
        const float zn = g_znorm[bm + lr];
        float best = 3.4e38f; int bi = 0;
#pragma unroll
        for (int j = 0; j < 8; ++j) {
            const float d = (zn + cn[j]) - 2.0f * acc[i][j];   // matches reference assoc.
            if (d < best) { best = d; bi = bn + tx * 8 + j; }  // strict < keeps first
        }
        sval[lr * 16 + tx] = best;
        sidx[lr * 16 + tx] = bi;
    }
    __syncthreads();
    if (tid < 128) {
        float best = 3.4e38f; int bi = 0;
#pragma unroll
        for (int t2 = 0; t2 < 16; ++t2) {  // ascending tx == ascending k
            const float vv = sval[tid * 16 + t2];
            if (vv < best) { best = vv; bi = sidx[tid * 16 + t2]; }
        }
        g_pval[(size_t)(bm + tid) * NCB + blockIdx.x] = best;
        g_pidx[(size_t)(bm + tid) * NCB + blockIdx.x] = bi;
    }
}

// reduce the 64 column-tile partials per row, in ascending column-block order
__global__ __launch_bounds__(256) void argmin_final()
{
    const int r = blockIdx.x * blockDim.x + threadIdx.x;
    const float* pv = &g_pval[(size_t)r * NCB];
    const int*   pi = &g_pidx[(size_t)r * NCB];
    float best = 3.4e38f; int bi = 0;
#pragma unroll 8
    for (int p = 0; p < NCB; ++p) {
        const float v = pv[p];
        if (v < best) { best = v; bi = pi[p]; }
    }
    g_bidx[r] = bi;
}

// out[r] = codebook[idx[r]]  (STE output equals the quantized codeword)
__global__ __launch_bounds__(256) void gather_out(
    const float* __restrict__ CB, float* __restrict__ out)
{
    const int r = blockIdx.x;
    const int k = g_bidx[r];
    const float4* src = (const float4*)(CB + (size_t)k * D_OUT);
    float4* dst = (float4*)(out + (size_t)r * D_OUT);
    for (int c = threadIdx.x; c < D_OUT / 4; c += 256) dst[c] = src[c];
}

// =====================================================================
extern "C" void kernel_launch(void* const* d_in, const int* in_sizes, int n_in,
                              void* d_out, int out_size)
{
    const float* latents = (const float*)d_in[0];
    const float* W1      = (const float*)d_in[1];
    const float* b1      = (const float*)d_in[2];
    const float* g1      = (const float*)d_in[3];
    const float* be1     = (const float*)d_in[4];
    const float* W2      = (const float*)d_in[5];
    const float* b2      = (const float*)d_in[6];
    const float* g2      = (const float*)d_in[7];
    const float* be2     = (const float*)d_in[8];
    const float* cb      = (const float*)d_in[9];
    float* out = (float*)d_out;

    float *hbuf = 0, *zbuf = 0;
    cudaGetSymbolAddress((void**)&hbuf, g_h);
    cudaGetSymbolAddress((void**)&zbuf, g_z);

    // 1) h = latents @ W1^T + b1
    sgemm_bias<<<dim3(D_H / 128, M_ROWS / 128), 256>>>(latents, W1, b1, hbuf,
                                                       M_ROWS, D_H, D_IN);
    // 2) h = gelu(layernorm(h))
    ln_gelu4096<<<M_ROWS, 256>>>(hbuf, g1, be1);
    // 3) z = h @ W2^T + b2
    sgemm_bias<<<dim3(D_OUT / 128, M_ROWS / 128), 256>>>(hbuf, W2, b2, zbuf,
                                                         M_ROWS, D_OUT, D_H);
    // 4) z = layernorm(z); znorm
    ln_znorm2048<<<M_ROWS, 256>>>(zbuf, g2, be2);
    // 5) codebook norms
    cnorm2048<<<KCB, 256>>>(cb);
    // 6) fused distance GEMM + tile argmin partials
    score_argmin<<<dim3(KCB / 128, M_ROWS / 128), 256>>>(zbuf, cb);
    // 7) final argmin per row
    argmin_final<<<M_ROWS / 256, 256>>>();
    // 8) gather codewords into output
    gather_out<<<M_ROWS, 256>>>(cb, out);
}

// round 2
// speedup vs baseline: 1.1230x; 1.1230x over previous
#include <cuda_runtime.h>
#include <math.h>

// Problem dims (fixed by the reference)
#define M_ROWS 8192      // B*L = 4*2048
#define D_IN   1536
#define D_H    4096
#define D_OUT  2048
#define KCB    8192      // codebook size
#define NCB    (KCB/128) // 64 column blocks in the score GEMM

// -------- scratch (device globals; no allocations allowed) ----------
__device__ float g_h[(size_t)M_ROWS * D_H];      // 134 MB
__device__ float g_z[(size_t)M_ROWS * D_OUT];    // 67 MB
__device__ float g_znorm[M_ROWS];
__device__ float g_cnorm[KCB];
__device__ float g_pval[(size_t)M_ROWS * NCB];
__device__ int   g_pidx[(size_t)M_ROWS * NCB];
__device__ int   g_bidx[M_ROWS];

// -------- tiling ----------
#define BK   16
#define SPAD 4
#define LDA  (128 + SPAD)   // 132 floats; keeps 16B alignment per k-row (132*4=528, 528%16==0)

typedef unsigned long long u64;

// packed f32x2 helpers (sm_100+; ptxas never emits these from C++)
__device__ __forceinline__ u64 dup_f32x2(float x)
{
    u64 r; asm("mov.b64 %0, {%1, %1};" : "=l"(r) : "f"(x)); return r;
}
__device__ __forceinline__ void fma_f32x2(u64& d, u64 a, u64 b)
{
    asm("fma.rn.f32x2 %0, %1, %2, %0;" : "+l"(d) : "l"(a), "l"(b));
}
__device__ __forceinline__ void unpack_f32x2(float& lo, float& hi, u64 v)
{
    asm("mov.b64 {%0, %1}, %2;" : "=f"(lo), "=f"(hi) : "l"(v));
}

// =====================================================================
// C[m][n] = sum_k A[m,k]*B[n,k] + bias[n]  (both operands K-major)
// 128x128 tile, BK=16, 256 threads, 8x8 per thread via packed f32x2
// (pairs along M, loaded directly as 64-bit from K-major smem).
// =====================================================================
__global__ __launch_bounds__(256) void sgemm_bias(
    const float* __restrict__ A, const float* __restrict__ B,
    const float* __restrict__ bias, float* __restrict__ C,
    int M, int N, int K)
{
    __shared__ float As[2][BK][LDA];
    __shared__ float Bs[2][BK][LDA];

    const int tid = threadIdx.x;
    const int tx  = tid & 15;
    const int ty  = tid >> 4;
    const int bm  = blockIdx.y * 128;
    const int bn  = blockIdx.x * 128;

    u64 acc2[4][8];   // [m-pair][n]; lane lo = row 2*i2, lane hi = row 2*i2+1
#pragma unroll
    for (int i = 0; i < 4; ++i)
#pragma unroll
        for (int j = 0; j < 8; ++j) acc2[i][j] = 0ull;

    const int r0 = tid >> 2;        // 0..63
    const int c4 = (tid & 3) * 4;   // 0,4,8,12

    float4 ra[2], rb[2];
    // prologue: tile 0
#pragma unroll
    for (int i = 0; i < 2; ++i) {
        int r = r0 + i * 64;
        ra[i] = *(const float4*)(A + (size_t)(bm + r) * K + c4);
        rb[i] = *(const float4*)(B + (size_t)(bn + r) * K + c4);
    }
#pragma unroll
    for (int i = 0; i < 2; ++i) {
        int r = r0 + i * 64;
#pragma unroll
        for (int j = 0; j < 4; ++j) {
            As[0][c4 + j][r] = ((const float*)&ra[i])[j];
            Bs[0][c4 + j][r] = ((const float*)&rb[i])[j];
        }
    }
    __syncthreads();

    const int nt = K / BK;
    for (int t = 0; t < nt; ++t) {
        const int cur = t & 1, nxt = cur ^ 1;
        if (t + 1 < nt) {
            const int k0 = (t + 1) * BK;
#pragma unroll
            for (int i = 0; i < 2; ++i) {
                int r = r0 + i * 64;
                ra[i] = *(const float4*)(A + (size_t)(bm + r) * K + k0 + c4);
                rb[i] = *(const float4*)(B + (size_t)(bn + r) * K + k0 + c4);
            }
        }
#pragma unroll
        for (int k = 0; k < BK; ++k) {
            // A rows are consecutive in smem -> natural 64-bit pairs, no packing
            const u64* ap = (const u64*)&As[cur][k][ty * 8];
            u64 a2[4];
            a2[0] = ap[0]; a2[1] = ap[1]; a2[2] = ap[2]; a2[3] = ap[3];
            float b[8];
            *(float4*)&b[0] = *(const float4*)&Bs[cur][k][tx * 8];
            *(float4*)&b[4] = *(const float4*)&Bs[cur][k][tx * 8 + 4];
            u64 bd[8];
#pragma unroll
            for (int j = 0; j < 8; ++j) bd[j] = dup_f32x2(b[j]);
#pragma unroll
            for (int i2 = 0; i2 < 4; ++i2)
#pragma unroll
                for (int j = 0; j < 8; ++j)
                    fma_f32x2(acc2[i2][j], a2[i2], bd[j]);
        }
        if (t + 1 < nt) {
#pragma unroll
            for (int i = 0; i < 2; ++i) {
                int r = r0 + i * 64;
#pragma unroll
                for (int j = 0; j < 4; ++j) {
                    As[nxt][c4 + j][r] = ((const float*)&ra[i])[j];
                    Bs[nxt][c4 + j][r] = ((const float*)&rb[i])[j];
                }
            }
        }
        __syncthreads();
    }

    // epilogue: unpack, + bias, vectorized stores
    const float4 bj0 = *(const float4*)(bias + bn + tx * 8);
    const float4 bj1 = *(const float4*)(bias + bn + tx * 8 + 4);
#pragma unroll
    for (int i2 = 0; i2 < 4; ++i2) {
        float lo[8], hi[8];
#pragma unroll
        for (int j = 0; j < 8; ++j) unpack_f32x2(lo[j], hi[j], acc2[i2][j]);

        const int gm0 = bm + ty * 8 + 2 * i2;
        float4 v0, v1;
        v0.x = lo[0] + bj0.x; v0.y = lo[1] + bj0.y;
        v0.z = lo[2] + bj0.z; v0.w = lo[3] + bj0.w;
        v1.x = lo[4] + bj1.x; v1.y = lo[5] + bj1.y;
        v1.z = lo[6] + bj1.z; v1.w = lo[7] + bj1.w;
        *(float4*)(C + (size_t)gm0 * N + bn + tx * 8)     = v0;
        *(float4*)(C + (size_t)gm0 * N + bn + tx * 8 + 4) = v1;
        v0.x = hi[0] + bj0.x; v0.y = hi[1] + bj0.y;
        v0.z = hi[2] + bj0.z; v0.w = hi[3] + bj0.w;
        v1.x = hi[4] + bj1.x; v1.y = hi[5] + bj1.y;
        v1.z = hi[6] + bj1.z; v1.w = hi[7] + bj1.w;
        *(float4*)(C + (size_t)(gm0 + 1) * N + bn + tx * 8)     = v0;
        *(float4*)(C + (size_t)(gm0 + 1) * N + bn + tx * 8 + 4) = v1;
    }
}

// =====================================================================
// Reductions / normalization
// =====================================================================
__device__ __forceinline__ float block_reduce_sum(float v)
{
    __shared__ float sh[8];
    const int lane = threadIdx.x & 31, w = threadIdx.x >> 5;
#pragma unroll
    for (int o = 16; o; o >>= 1) v += __shfl_xor_sync(0xffffffffu, v, o);
    if (lane == 0) sh[w] = v;
    __syncthreads();
    if (w == 0) {
        float x = (lane < 8) ? sh[lane] : 0.f;
#pragma unroll
        for (int o = 4; o; o >>= 1) x += __shfl_xor_sync(0xffffffffu, x, o);
        if (lane == 0) sh[0] = x;
    }
    __syncthreads();
    float r = sh[0];
    __syncthreads();   // protect sh before next call
    return r;
}

__device__ __forceinline__ float gelu_exact(float y)
{
    return 0.5f * y * (1.0f + erff(y * 0.70710678118654752440f));
}

// per-row LN (two-pass, matching reference) then exact GELU, in place. D=4096.
__global__ __launch_bounds__(256) void ln_gelu4096(
    float* __restrict__ H, const float* __restrict__ gm, const float* __restrict__ bt)
{
    float* x = H + (size_t)blockIdx.x * D_H;
    const int tid = threadIdx.x;
    float v[16];
#pragma unroll
    for (int i = 0; i < 4; ++i)
        *(float4*)&v[i * 4] = *(const float4*)(x + tid * 4 + i * 1024);
    float s = 0.f;
#pragma unroll
    for (int i = 0; i < 16; ++i) s += v[i];
    s = block_reduce_sum(s);
    const float mu = s * (1.0f / 4096.0f);
    float q = 0.f;
#pragma unroll
    for (int i = 0; i < 16; ++i) { float d = v[i] - mu; q += d * d; }
    q = block_reduce_sum(q);
    const float inv = 1.0f / sqrtf(q * (1.0f / 4096.0f) + 1e-5f);
#pragma unroll
    for (int i = 0; i < 4; ++i) {
        const float4 gg = *(const float4*)(gm + tid * 4 + i * 1024);
        const float4 bb = *(const float4*)(bt + tid * 4 + i * 1024);
        float4 o;
        o.x = gelu_exact((v[i*4+0] - mu) * inv * gg.x + bb.x);
        o.y = gelu_exact((v[i*4+1] - mu) * inv * gg.y + bb.y);
        o.z = gelu_exact((v[i*4+2] - mu) * inv * gg.z + bb.z);
        o.w = gelu_exact((v[i*4+3] - mu) * inv * gg.w + bb.w);
        *(float4*)(x + tid * 4 + i * 1024) = o;
    }
}

// per-row LN for z (D=2048), in place; also writes znorm = sum(zf*zf)
__global__ __launch_bounds__(256) void ln_znorm2048(
    float* __restrict__ Z, const float* __restrict__ gm, const float* __restrict__ bt)
{
    float* x = Z + (size_t)blockIdx.x * D_OUT;
    const int tid = threadIdx.x;
    float v[8];
#pragma unroll
    for (int i = 0; i < 2; ++i)
        *(float4*)&v[i * 4] = *(const float4*)(x + tid * 4 + i * 1024);
    float s = 0.f;
#pragma unroll
    for (int i = 0; i < 8; ++i) s += v[i];
    s = block_reduce_sum(s);
    const float mu = s * (1.0f / 2048.0f);
    float q = 0.f;
#pragma unroll
    for (int i = 0; i < 8; ++i) { float d = v[i] - mu; q += d * d; }
    q = block_reduce_sum(q);
    const float inv = 1.0f / sqrtf(q * (1.0f / 2048.0f) + 1e-5f);
    float nrm = 0.f;
#pragma unroll
    for (int i = 0; i < 2; ++i) {
        const float4 gg = *(const float4*)(gm + tid * 4 + i * 1024);
        const float4 bb = *(const float4*)(bt + tid * 4 + i * 1024);
        float4 o;
        o.x = (v[i*4+0] - mu) * inv * gg.x + bb.x;
        o.y = (v[i*4+1] - mu) * inv * gg.y + bb.y;
        o.z = (v[i*4+2] - mu) * inv * gg.z + bb.z;
        o.w = (v[i*4+3] - mu) * inv * gg.w + bb.w;
        nrm += o.x*o.x + o.y*o.y + o.z*o.z + o.w*o.w;
        *(float4*)(x + tid * 4 + i * 1024) = o;
    }
    nrm = block_reduce_sum(nrm);
    if (tid == 0) g_znorm[blockIdx.x] = nrm;
}

// ||codebook_k||^2 for all k
__global__ __launch_bounds__(256) void cnorm2048(const float* __restrict__ CB)
{
    const float* c = CB + (size_t)blockIdx.x * D_OUT;
    float s = 0.f;
#pragma unroll
    for (int i = 0; i < 2; ++i) {
        const float4 u = *(const float4*)(c + threadIdx.x * 4 + i * 1024);
        s += u.x*u.x + u.y*u.y + u.z*u.z + u.w*u.w;
    }
    s = block_reduce_sum(s);
    if (threadIdx.x == 0) g_cnorm[blockIdx.x] = s;
}

// =====================================================================
// Score GEMM (packed f32x2) with fused per-(rowtile,coltile) argmin.
// dist = (znorm + cnorm) - 2*dot, first-min tie-break (ascending k).
// =====================================================================
__global__ __launch_bounds__(256) void score_argmin(
    const float* __restrict__ A,   // z  [8192, 2048]
    const float* __restrict__ B)   // cb [8192, 2048]
{
    __shared__ float As[2][BK][LDA];
    __shared__ float Bs[2][BK][LDA];

    const int tid = threadIdx.x;
    const int tx  = tid & 15;
    const int ty  = tid >> 4;
    const int bm  = blockIdx.y * 128;
    const int bn  = blockIdx.x * 128;
    const int K   = D_OUT;

    u64 acc2[4][8];
#pragma unroll
    for (int i = 0; i < 4; ++i)
#pragma unroll
        for (int j = 0; j < 8; ++j) acc2[i][j] = 0ull;

    const int r0 = tid >> 2;
    const int c4 = (tid & 3) * 4;

    float4 ra[2], rb[2];
#pragma unroll
    for (int i = 0; i < 2; ++i) {
        int r = r0 + i * 64;
        ra[i] = *(const float4*)(A + (size_t)(bm + r) * K + c4);
        rb[i] = *(const float4*)(B + (size_t)(bn + r) * K + c4);
    }
#pragma unroll
    for (int i = 0; i < 2; ++i) {
        int r = r0 + i * 64;
#pragma unroll
        for (int j = 0; j < 4; ++j) {
            As[0][c4 + j][r] = ((const float*)&ra[i])[j];
            Bs[0][c4 + j][r] = ((const float*)&rb[i])[j];
        }
    }
    __syncthreads();

    const int nt = K / BK;
    for (int t = 0; t < nt; ++t) {
        const int cur = t & 1, nxt = cur ^ 1;
        if (t + 1 < nt) {
            const int k0 = (t + 1) * BK;
#pragma unroll
            for (int i = 0; i < 2; ++i) {
                int r = r0 + i * 64;
                ra[i] = *(const float4*)(A + (size_t)(bm + r) * K + k0 + c4);
                rb[i] = *(const float4*)(B + (size_t)(bn + r) * K + k0 + c4);
            }
        }
#pragma unroll
        for (int k = 0; k < BK; ++k) {
            const u64* ap = (const u64*)&As[cur][k][ty * 8];
            u64 a2[4];
            a2[0] = ap[0]; a2[1] = ap[1]; a2[2] = ap[2]; a2[3] = ap[3];
            float b[8];
            *(float4*)&b[0] = *(const float4*)&Bs[cur][k][tx * 8];
            *(float4*)&b[4] = *(const float4*)&Bs[cur][k][tx * 8 + 4];
            u64 bd[8];
#pragma unroll
            for (int j = 0; j < 8; ++j) bd[j] = dup_f32x2(b[j]);
#pragma unroll
            for (int i2 = 0; i2 < 4; ++i2)
#pragma unroll
                for (int j = 0; j < 8; ++j)
                    fma_f32x2(acc2[i2][j], a2[i2], bd[j]);
        }
        if (t + 1 < nt) {
#pragma unroll
            for (int i = 0; i < 2; ++i) {
                int r = r0 + i * 64;
#pragma unroll
                for (int j = 0; j < 4; ++j) {
                    As[nxt][c4 + j][r] = ((const float*)&ra[i])[j];
                    Bs[nxt][c4 + j][r] = ((const float*)&rb[i])[j];
                }
            }
        }
        __syncthreads();
    }

    // epilogue: distances + per-row argmin across the 128-wide column tile
    __syncthreads();
    float* sval = (float*)As;   // 128*16 floats fits in As
    int*   sidx = (int*)Bs;

    float cn[8];
#pragma unroll
    for (int j = 0; j < 8; ++j) cn[j] = g_cnorm[bn + tx * 8 + j];

#pragma unroll
    for (int i2 = 0; i2 < 4; ++i2) {
        float lo[8], hi[8];
#pragma unroll
        for (int j = 0; j < 8; ++j) unpack_f32x2(lo[j], hi[j], acc2[i2][j]);
#pragma unroll
        for (int half = 0; half < 2; ++half) {
            const float* accr = half ? hi : lo;
            const int lr = ty * 8 + 2 * i2 + half;
            const float zn = g_znorm[bm + lr];
            float best = 3.4e38f; int bi = 0;
#pragma unroll
            for (int j = 0; j < 8; ++j) {
                const float d = (zn + cn[j]) - 2.0f * accr[j];   // matches reference assoc.
                if (d < best) { best = d; bi = bn + tx * 8 + j; } // strict < keeps first
            }
            sval[lr * 16 + tx] = best;
            sidx[lr * 16 + tx] = bi;
        }
    }
    __syncthreads();
    if (tid < 128) {
        float best = 3.4e38f; int bi = 0;
#pragma unroll
        for (int t2 = 0; t2 < 16; ++t2) {  // ascending tx == ascending k
            const float vv = sval[tid * 16 + t2];
            if (vv < best) { best = vv; bi = sidx[tid * 16 + t2]; }
        }
        g_pval[(size_t)(bm + tid) * NCB + blockIdx.x] = best;
        g_pidx[(size_t)(bm + tid) * NCB + blockIdx.x] = bi;
    }
}

// reduce the 64 column-tile partials per row, in ascending column-block order
__global__ __launch_bounds__(256) void argmin_final()
{
    const int r = blockIdx.x * blockDim.x + threadIdx.x;
    const float* pv = &g_pval[(size_t)r * NCB];
    const int*   pi = &g_pidx[(size_t)r * NCB];
    float best = 3.4e38f; int bi = 0;
#pragma unroll 8
    for (int p = 0; p < NCB; ++p) {
        const float v = pv[p];
        if (v < best) { best = v; bi = pi[p]; }
    }
    g_bidx[r] = bi;
}

// out[r] = codebook[idx[r]]  (STE output equals the quantized codeword)
__global__ __launch_bounds__(256) void gather_out(
    const float* __restrict__ CB, float* __restrict__ out)
{
    const int r = blockIdx.x;
    const int k = g_bidx[r];
    const float4* src = (const float4*)(CB + (size_t)k * D_OUT);
    float4* dst = (float4*)(out + (size_t)r * D_OUT);
    for (int c = threadIdx.x; c < D_OUT / 4; c += 256) dst[c] = src[c];
}

// =====================================================================
extern "C" void kernel_launch(void* const* d_in, const int* in_sizes, int n_in,
                              void* d_out, int out_size)
{
    const float* latents = (const float*)d_in[0];
    const float* W1      = (const float*)d_in[1];
    const float* b1      = (const float*)d_in[2];
    const float* g1      = (const float*)d_in[3];
    const float* be1     = (const float*)d_in[4];
    const float* W2      = (const float*)d_in[5];
    const float* b2      = (const float*)d_in[6];
    const float* g2      = (const float*)d_in[7];
    const float* be2     = (const float*)d_in[8];
    const float* cb      = (const float*)d_in[9];
    float* out = (float*)d_out;

    float *hbuf = 0, *zbuf = 0;
    cudaGetSymbolAddress((void**)&hbuf, g_h);
    cudaGetSymbolAddress((void**)&zbuf, g_z);

    // 1) h = latents @ W1^T + b1
    sgemm_bias<<<dim3(D_H / 128, M_ROWS / 128), 256>>>(latents, W1, b1, hbuf,
                                                       M_ROWS, D_H, D_IN);
    // 2) h = gelu(layernorm(h))
    ln_gelu4096<<<M_ROWS, 256>>>(hbuf, g1, be1);
    // 3) z = h @ W2^T + b2
    sgemm_bias<<<dim3(D_OUT / 128, M_ROWS / 128), 256>>>(hbuf, W2, b2, zbuf,
                                                         M_ROWS, D_OUT, D_H);
    // 4) z = layernorm(z); znorm
    ln_znorm2048<<<M_ROWS, 256>>>(zbuf, g2, be2);
    // 5) codebook norms
    cnorm2048<<<KCB, 256>>>(cb);
    // 6) fused distance GEMM + tile argmin partials
    score_argmin<<<dim3(KCB / 128, M_ROWS / 128), 256>>>(zbuf, cb);
    // 7) final argmin per row
    argmin_final<<<M_ROWS / 256, 256>>>();
    // 8) gather codewords into output
    gather_out<<<M_ROWS, 256>>>(cb, out);
}